// round 1
// baseline (speedup 1.0000x reference)
#include <cuda_runtime.h>

#define LSEQ 96
#define DM 32

// One warp processes one (b,n) tile of [96 x 32]. lane == channel d.
// 2 warps per 64-thread block; grid = 16000/2 = 8000 blocks.
__global__ __launch_bounds__(64, 8)
void feldm_kernel(const float* __restrict__ x,
                  const float* __restrict__ Wq,
                  const float* __restrict__ Wo,
                  const float* __restrict__ bo,
                  const float* __restrict__ W1,
                  const float* __restrict__ W2,
                  float* __restrict__ out)
{
    __shared__ float trig[LSEQ][8];        // cos0,sin0,cos1,sin1,cos2,sin2,pad,pad
    __shared__ float xrbuf[2][LSEQ][DM];   // per-warp residual buffer (conflict-free)
    __shared__ float scr[2][DM][8];        // per-warp 3-mode complex exchange buffer

    const int tid  = threadIdx.x;
    const int warp = tid >> 5;
    const int lane = tid & 31;

    // ---- one-time trig table (3 modes x 96 steps), double-precision angles ----
    {
        const int freqs[3] = {1, 4, 5};
        for (int i = tid; i < LSEQ * 3; i += 64) {
            int l = i % LSEQ;
            int m = i / LSEQ;
            double ang = (2.0 * 3.14159265358979323846 * (double)(freqs[m] * l)) / 96.0;
            double s, c;
            sincos(ang, &s, &c);
            trig[l][2 * m]     = (float)c;
            trig[l][2 * m + 1] = (float)s;
        }
    }
    __syncthreads();

    const int unit = blockIdx.x * 2 + warp;     // b*2000 + n, 0..15999
    const int n    = unit % 2000;
    const float* __restrict__ xu = x   + (size_t)unit * (LSEQ * DM);
    float* __restrict__       ou = out + (size_t)unit * (LSEQ * DM);

    // ---- Phase B: 3-mode DFT of x along l, per channel d = lane (rfft sign: e^{-iwl}) ----
    float ar0 = 0.f, ai0 = 0.f, ar1 = 0.f, ai1 = 0.f, ar2 = 0.f, ai2 = 0.f;
    #pragma unroll 4
    for (int l = 0; l < LSEQ; ++l) {
        float xv = xu[l * DM + lane];               // coalesced 128B per warp
        float4 t0 = *(const float4*)&trig[l][0];    // broadcast
        float2 t1 = *(const float2*)&trig[l][4];
        ar0 = fmaf(xv, t0.x, ar0); ai0 = fmaf(-xv, t0.y, ai0);
        ar1 = fmaf(xv, t0.z, ar1); ai1 = fmaf(-xv, t0.w, ai1);
        ar2 = fmaf(xv, t1.x, ar2); ai2 = fmaf(-xv, t1.y, ai2);
    }
    *(float4*)&scr[warp][lane][0] = make_float4(ar0, ai0, ar1, ai1);
    *(float2*)&scr[warp][lane][4] = make_float2(ar2, ai2);
    __syncwarp();

    // ---- Phase C: Xq[c,m] = sum_d Wq[c,d] * Xx[d,m]  (bq drops: modes >= 1) ----
    float wrow[32];
    #pragma unroll
    for (int j = 0; j < 8; ++j) {
        float4 v = *(const float4*)&Wq[lane * 32 + 4 * j];
        wrow[4*j] = v.x; wrow[4*j+1] = v.y; wrow[4*j+2] = v.z; wrow[4*j+3] = v.w;
    }
    float qr0=0.f,qi0=0.f,qr1=0.f,qi1=0.f,qr2=0.f,qi2=0.f;
    #pragma unroll 8
    for (int d = 0; d < 32; ++d) {
        float4 t0 = *(const float4*)&scr[warp][d][0];   // broadcast
        float2 t1 = *(const float2*)&scr[warp][d][4];
        float w = wrow[d];
        qr0 = fmaf(w, t0.x, qr0); qi0 = fmaf(w, t0.y, qi0);
        qr1 = fmaf(w, t0.z, qr1); qi1 = fmaf(w, t0.w, qi1);
        qr2 = fmaf(w, t1.x, qr2); qi2 = fmaf(w, t1.y, qi2);
    }
    __syncwarp();
    *(float4*)&scr[warp][lane][0] = make_float4(qr0, qi0, qr1, qi1);
    *(float2*)&scr[warp][lane][4] = make_float2(qr2, qi2);
    __syncwarp();

    // ---- Phase D: per-head complex 8x8: O[(h,o),m] = sum_e Xq[(h,e),m]*(W1+iW2)[n,h,e,o,m] ----
    const int h = lane >> 3, o = lane & 7;
    const float* __restrict__ w1p = W1 + ((size_t)n * 4 + h) * 192;
    const float* __restrict__ w2p = W2 + ((size_t)n * 4 + h) * 192;
    float or0=0.f,oi0=0.f,or1=0.f,oi1=0.f,or2=0.f,oi2=0.f;
    #pragma unroll
    for (int e = 0; e < 8; ++e) {
        float4 t0 = *(const float4*)&scr[warp][h * 8 + e][0];
        float2 t1 = *(const float2*)&scr[warp][h * 8 + e][4];
        int widx = (e * 8 + o) * 3;
        float a0 = w1p[widx+0], a1 = w1p[widx+1], a2 = w1p[widx+2];
        float b0 = w2p[widx+0], b1 = w2p[widx+1], b2 = w2p[widx+2];
        or0 += t0.x*a0 - t0.y*b0;  oi0 += t0.x*b0 + t0.y*a0;
        or1 += t0.z*a1 - t0.w*b1;  oi1 += t0.z*b1 + t0.w*a1;
        or2 += t1.x*a2 - t1.y*b2;  oi2 += t1.x*b2 + t1.y*a2;
    }
    __syncwarp();
    *(float4*)&scr[warp][lane][0] = make_float4(or0, oi0, or1, oi1);
    *(float2*)&scr[warp][lane][4] = make_float2(or2, oi2);
    __syncwarp();

    // ---- Phase E: Z[dout,m] = sum_c O[c,m] * Wo[dout,c] ----
    #pragma unroll
    for (int j = 0; j < 8; ++j) {
        float4 v = *(const float4*)&Wo[lane * 32 + 4 * j];
        wrow[4*j] = v.x; wrow[4*j+1] = v.y; wrow[4*j+2] = v.z; wrow[4*j+3] = v.w;
    }
    float zr0=0.f,zi0=0.f,zr1=0.f,zi1=0.f,zr2=0.f,zi2=0.f;
    #pragma unroll 8
    for (int c = 0; c < 32; ++c) {
        float4 t0 = *(const float4*)&scr[warp][c][0];
        float2 t1 = *(const float2*)&scr[warp][c][4];
        float w = wrow[c];
        zr0 = fmaf(w, t0.x, zr0); zi0 = fmaf(w, t0.y, zi0);
        zr1 = fmaf(w, t0.z, zr1); zi1 = fmaf(w, t0.w, zi1);
        zr2 = fmaf(w, t1.x, zr2); zi2 = fmaf(w, t1.y, zi2);
    }
    const float inv = 2.0f / 96.0f;    // irfft factor, interior modes
    zr0 *= inv; zi0 *= inv; zr1 *= inv; zi1 *= inv; zr2 *= inv; zi2 *= inv;
    const float bias = bo[lane];

    // ---- Phase F: inverse transform + out-projection bias + residual -> xr in smem ----
    #pragma unroll 4
    for (int l = 0; l < LSEQ; ++l) {
        float4 t0 = *(const float4*)&trig[l][0];
        float2 t1 = *(const float2*)&trig[l][4];
        float y = zr0*t0.x - zi0*t0.y + zr1*t0.z - zi1*t0.w + zr2*t1.x - zi2*t1.y;
        float xr = xu[l * DM + lane] + y + bias;    // L1/L2 re-read of x
        xrbuf[warp][l][lane] = xr;
    }
    __syncwarp();

    // ---- Phase G: k=25 edge-replicated moving average (sliding window) + output ----
    const float x0  = xrbuf[warp][0][lane];
    const float x95 = xrbuf[warp][95][lane];
    float run = 12.0f * x0;                      // left pad: 12 replicas of xr[0]
    #pragma unroll
    for (int j = 0; j <= 12; ++j) run += xrbuf[warp][j][lane];
    const float inv25 = 1.0f / 25.0f;
    for (int l = 0; l < LSEQ; ++l) {
        float cur = xrbuf[warp][l][lane];
        ou[l * DM + lane] = cur - run * inv25;   // res = xr - trend, coalesced store
        float add = (l + 13 <= 95) ? xrbuf[warp][l + 13][lane] : x95;
        float sub = (l - 12 >= 0)  ? xrbuf[warp][l - 12][lane] : x0;
        run += add - sub;
    }
}

extern "C" void kernel_launch(void* const* d_in, const int* in_sizes, int n_in,
                              void* d_out, int out_size) {
    // metadata order: x, Wq, bq, Wk, bk, Wv, bv, Wo, bo, W1, W2
    const float* x  = (const float*)d_in[0];
    const float* Wq = (const float*)d_in[1];
    const float* Wo = (const float*)d_in[7];
    const float* bo = (const float*)d_in[8];
    const float* W1 = (const float*)d_in[9];
    const float* W2 = (const float*)d_in[10];
    feldm_kernel<<<8000, 64>>>(x, Wq, Wo, bo, W1, W2, (float*)d_out);
}

// round 3
// speedup vs baseline: 1.7310x; 1.7310x over previous
#include <cuda_runtime.h>
#include <cstdint>

#define LSEQ 96
#define DM 32

__device__ __forceinline__ void cp_async16(unsigned int saddr, const void* gaddr) {
    asm volatile("cp.async.cg.shared.global [%0], [%1], 16;\n" :: "r"(saddr), "l"(gaddr));
}
__device__ __forceinline__ void cp_commit() {
    asm volatile("cp.async.commit_group;\n" ::: "memory");
}
__device__ __forceinline__ void cp_wait0() {
    asm volatile("cp.async.wait_group 0;\n" ::: "memory");
}

// One warp per (b,n) tile of [96 x 32], lane == channel d.
// 2 warps / 64-thread block; grid = 8000.  smem: 27.75KB -> 8 blocks/SM.
__global__ __launch_bounds__(64, 8)
void feldm_kernel(const float* __restrict__ x,
                  const float* __restrict__ Wq,
                  const float* __restrict__ Wo,
                  const float* __restrict__ bo,
                  const float* __restrict__ W1,
                  const float* __restrict__ W2,
                  float* __restrict__ out)
{
    __shared__ float4 trig4[LSEQ];          // cos0,sin0,cos1,sin1
    __shared__ float2 trig2[LSEQ];          // cos2,sin2
    __shared__ float  xbuf[2][LSEQ * DM];   // per-warp x tile, then xr in place (12KB each)
    __shared__ float4 scr4[2][DM];          // 3-mode complex exchange (modes 0,1)
    __shared__ float2 scr2[2][DM];          // mode 2

    const int tid  = threadIdx.x;
    const int warp = tid >> 5;
    const int lane = tid & 31;

    const int unit = blockIdx.x * 2 + warp;     // b*2000 + n
    const int n    = unit % 2000;
    const float* __restrict__ xu = x   + (size_t)unit * (LSEQ * DM);
    float* __restrict__       ou = out + (size_t)unit * (LSEQ * DM);

    // ---- stage x tile into smem with cp.async (24 x 16B per lane, full MLP) ----
    {
        unsigned int sbase = (unsigned int)__cvta_generic_to_shared(&xbuf[warp][0]);
        const float4* gsrc = (const float4*)xu;
        #pragma unroll
        for (int k = 0; k < 24; ++k) {
            int idx = k * 32 + lane;                 // float4 index, coalesced
            cp_async16(sbase + idx * 16, gsrc + idx);
        }
        cp_commit();
    }

    // ---- trig table (overlaps the async copy) ----
    {
        const int freqs[3] = {1, 4, 5};
        for (int i = tid; i < LSEQ; i += 64) {
            double s0, c0, s1, c1, s2, c2;
            const double w = 2.0 * 3.14159265358979323846 / 96.0;
            sincos(w * (double)(freqs[0] * i), &s0, &c0);
            sincos(w * (double)(freqs[1] * i), &s1, &c1);
            sincos(w * (double)(freqs[2] * i), &s2, &c2);
            trig4[i] = make_float4((float)c0, (float)s0, (float)c1, (float)s1);
            trig2[i] = make_float2((float)c2, (float)s2);
        }
    }
    __syncthreads();
    cp_wait0();
    __syncwarp();

    // ---- Phase B: 3-mode DFT along l (rfft sign e^{-iwl}), channel d = lane ----
    float ar0 = 0.f, ai0 = 0.f, ar1 = 0.f, ai1 = 0.f, ar2 = 0.f, ai2 = 0.f;
    #pragma unroll 8
    for (int l = 0; l < LSEQ; ++l) {
        float xv  = xbuf[warp][l * DM + lane];   // conflict-free LDS
        float4 t0 = trig4[l];                    // broadcast
        float2 t1 = trig2[l];
        ar0 = fmaf(xv, t0.x, ar0); ai0 = fmaf(-xv, t0.y, ai0);
        ar1 = fmaf(xv, t0.z, ar1); ai1 = fmaf(-xv, t0.w, ai1);
        ar2 = fmaf(xv, t1.x, ar2); ai2 = fmaf(-xv, t1.y, ai2);
    }
    scr4[warp][lane] = make_float4(ar0, ai0, ar1, ai1);
    scr2[warp][lane] = make_float2(ar2, ai2);
    __syncwarp();

    // ---- Phase C: Xq[c,m] = sum_d Wq[c,d] * Xx[d,m]  (bq only feeds mode 0) ----
    float wrow[32];
    #pragma unroll
    for (int j = 0; j < 8; ++j) {
        float4 v = *(const float4*)&Wq[lane * 32 + 4 * j];
        wrow[4*j] = v.x; wrow[4*j+1] = v.y; wrow[4*j+2] = v.z; wrow[4*j+3] = v.w;
    }
    float qr0=0.f,qi0=0.f,qr1=0.f,qi1=0.f,qr2=0.f,qi2=0.f;
    #pragma unroll
    for (int d = 0; d < 32; ++d) {
        float4 t0 = scr4[warp][d];               // broadcast
        float2 t1 = scr2[warp][d];
        float w = wrow[d];
        qr0 = fmaf(w, t0.x, qr0); qi0 = fmaf(w, t0.y, qi0);
        qr1 = fmaf(w, t0.z, qr1); qi1 = fmaf(w, t0.w, qi1);
        qr2 = fmaf(w, t1.x, qr2); qi2 = fmaf(w, t1.y, qi2);
    }
    __syncwarp();
    scr4[warp][lane] = make_float4(qr0, qi0, qr1, qi1);
    scr2[warp][lane] = make_float2(qr2, qi2);
    __syncwarp();

    // ---- Phase D: per-head complex 8x8 mix with (W1 + i W2)[n,h,:,:,m] ----
    const int h = lane >> 3, o = lane & 7;
    const float* __restrict__ w1p = W1 + ((size_t)n * 4 + h) * 192;
    const float* __restrict__ w2p = W2 + ((size_t)n * 4 + h) * 192;
    float or0=0.f,oi0=0.f,or1=0.f,oi1=0.f,or2=0.f,oi2=0.f;
    #pragma unroll
    for (int e = 0; e < 8; ++e) {
        float4 t0 = scr4[warp][h * 8 + e];
        float2 t1 = scr2[warp][h * 8 + e];
        int widx = (e * 8 + o) * 3;
        float a0 = w1p[widx+0], a1 = w1p[widx+1], a2 = w1p[widx+2];
        float b0 = w2p[widx+0], b1 = w2p[widx+1], b2 = w2p[widx+2];
        or0 += t0.x*a0 - t0.y*b0;  oi0 += t0.x*b0 + t0.y*a0;
        or1 += t0.z*a1 - t0.w*b1;  oi1 += t0.z*b1 + t0.w*a1;
        or2 += t1.x*a2 - t1.y*b2;  oi2 += t1.x*b2 + t1.y*a2;
    }
    __syncwarp();
    scr4[warp][lane] = make_float4(or0, oi0, or1, oi1);
    scr2[warp][lane] = make_float2(or2, oi2);
    __syncwarp();

    // ---- Phase E: Z[dout,m] = sum_c O[c,m] * Wo[dout,c] ----
    #pragma unroll
    for (int j = 0; j < 8; ++j) {
        float4 v = *(const float4*)&Wo[lane * 32 + 4 * j];
        wrow[4*j] = v.x; wrow[4*j+1] = v.y; wrow[4*j+2] = v.z; wrow[4*j+3] = v.w;
    }
    float zr0=0.f,zi0=0.f,zr1=0.f,zi1=0.f,zr2=0.f,zi2=0.f;
    #pragma unroll
    for (int c = 0; c < 32; ++c) {
        float4 t0 = scr4[warp][c];
        float2 t1 = scr2[warp][c];
        float w = wrow[c];
        zr0 = fmaf(w, t0.x, zr0); zi0 = fmaf(w, t0.y, zi0);
        zr1 = fmaf(w, t0.z, zr1); zi1 = fmaf(w, t0.w, zi1);
        zr2 = fmaf(w, t1.x, zr2); zi2 = fmaf(w, t1.y, zi2);
    }
    const float inv = 2.0f / 96.0f;     // irfft factor (interior modes)
    zr0 *= inv; zi0 *= inv; zr1 *= inv; zi1 *= inv; zr2 *= inv; zi2 *= inv;
    const float bias = bo[lane];

    // ---- Phase F: inverse 3-mode transform + bias + residual, in-place into xbuf ----
    #pragma unroll 8
    for (int l = 0; l < LSEQ; ++l) {
        float4 t0 = trig4[l];
        float2 t1 = trig2[l];
        float y  = zr0*t0.x - zi0*t0.y + zr1*t0.z - zi1*t0.w + zr2*t1.x - zi2*t1.y;
        float xr = xbuf[warp][l * DM + lane] + y + bias;
        xbuf[warp][l * DM + lane] = xr;        // same lane slot: no sync needed
    }

    // ---- Phase G: k=25 edge-replicated moving average (sliding window) + store ----
    const float x0  = xbuf[warp][0 * DM + lane];
    const float x95 = xbuf[warp][95 * DM + lane];
    float run = 12.0f * x0;
    #pragma unroll
    for (int j = 0; j <= 12; ++j) run += xbuf[warp][j * DM + lane];
    const float inv25 = 1.0f / 25.0f;
    for (int l = 0; l < LSEQ; ++l) {
        float cur = xbuf[warp][l * DM + lane];
        ou[l * DM + lane] = cur - run * inv25;                     // coalesced store
        float add = (l + 13 <= 95) ? xbuf[warp][(l + 13) * DM + lane] : x95;
        float sub = (l - 12 >= 0)  ? xbuf[warp][(l - 12) * DM + lane] : x0;
        run += add - sub;
    }
}

extern "C" void kernel_launch(void* const* d_in, const int* in_sizes, int n_in,
                              void* d_out, int out_size) {
    // metadata order: x, Wq, bq, Wk, bk, Wv, bv, Wo, bo, W1, W2
    const float* x  = (const float*)d_in[0];
    const float* Wq = (const float*)d_in[1];
    const float* Wo = (const float*)d_in[7];
    const float* bo = (const float*)d_in[8];
    const float* W1 = (const float*)d_in[9];
    const float* W2 = (const float*)d_in[10];
    feldm_kernel<<<8000, 64>>>(x, Wq, Wo, bo, W1, W2, (float*)d_out);
}

// round 5
// speedup vs baseline: 4.1505x; 2.3977x over previous
#include <cuda_runtime.h>
#include <cstdint>

#define LSEQ 96
#define DM 32

// ---------------- compile-time trig (constexpr Taylor, exact to ~1e-12) ----------------
__host__ __device__ constexpr double KPI = 3.14159265358979323846;
__host__ __device__ constexpr double tsin_(double x){ double x2=x*x;
  return x*(1 - x2/6*(1 - x2/20*(1 - x2/42*(1 - x2/72*(1 - x2/110*(1 - x2/156*(1 - x2/210)))))));
}
__host__ __device__ constexpr double tcos_(double x){ double x2=x*x;
  return 1 - x2/2*(1 - x2/12*(1 - x2/30*(1 - x2/56*(1 - x2/90*(1 - x2/132*(1 - x2/182))))));
}
__host__ __device__ constexpr double cs96(int k){ k=((k%96)+96)%96; int q=k/24, r=k%24; double x=r*(KPI/48);
  double c=tcos_(x), s=tsin_(x);
  return q==0? c : (q==1? -s : (q==2? -c : s)); }
__host__ __device__ constexpr double sn96(int k){ k=((k%96)+96)%96; int q=k/24, r=k%24; double x=r*(KPI/48);
  double c=tcos_(x), s=tsin_(x);
  return q==0? s : (q==1? c : (q==2? -s : -c)); }

// G_m(t) = e^{i w t} - (1/25)( sum_{j=lo..hi} e^{i w j} + Lpad + Rpad e^{i w 95} )
// (edge-replicated moving-average detrend folded into one complex constant per mode/t)
__host__ __device__ constexpr double Gre_(int f, int t){
  int lo = (t-12 < 0) ? 0 : t-12;
  int hi = (t+12 > 95) ? 95 : t+12;
  double s = 0;
  for (int j = lo; j <= hi; ++j) s += cs96(f*j);
  if (t < 12)  s += (double)(12 - t) * cs96(0);
  if (t > 83)  s += (double)(t - 83) * cs96(f*95);
  return cs96(f*t) - s/25.0;
}
__host__ __device__ constexpr double Gim_(int f, int t){
  int lo = (t-12 < 0) ? 0 : t-12;
  int hi = (t+12 > 95) ? 95 : t+12;
  double s = 0;
  for (int j = lo; j <= hi; ++j) s += sn96(f*j);
  if (t < 12)  s += (double)(12 - t) * sn96(0);
  if (t > 83)  s += (double)(t - 83) * sn96(f*95);
  return sn96(f*t) - s/25.0;
}

// ---------------- cp.async helpers ----------------
__device__ __forceinline__ void cp_async16(unsigned int saddr, const void* gaddr) {
    asm volatile("cp.async.cg.shared.global [%0], [%1], 16;\n" :: "r"(saddr), "l"(gaddr));
}
__device__ __forceinline__ void cp_commit(){ asm volatile("cp.async.commit_group;\n" ::: "memory"); }
__device__ __forceinline__ void cp_wait0(){ asm volatile("cp.async.wait_group 0;\n" ::: "memory"); }

// ---------------- Phase B: 3-mode DFT with immediate trig ----------------
struct Acc6 { float ar0, ai0, ar1, ai1, ar2, ai2; };

template<int L> __device__ __forceinline__ void bstep(Acc6& a, const float* xp){
  float xv = xp[L*DM];
  constexpr float c0=(float)cs96(1*L), s0=(float)sn96(1*L);
  constexpr float c1=(float)cs96(4*L), s1=(float)sn96(4*L);
  constexpr float c2=(float)cs96(5*L), s2=(float)sn96(5*L);
  a.ar0=fmaf(xv,c0,a.ar0); a.ai0=fmaf(xv,-s0,a.ai0);
  a.ar1=fmaf(xv,c1,a.ar1); a.ai1=fmaf(xv,-s1,a.ai1);
  a.ar2=fmaf(xv,c2,a.ar2); a.ai2=fmaf(xv,-s2,a.ai2);
}
template<int L> __device__ __forceinline__ void bloop(Acc6& a, const float* xp){
  if constexpr (L < LSEQ){ bstep<L>(a, xp); bloop<L+1>(a, xp); }
}

// ---------------- fused inverse-transform + detrend (Phases F+G) ----------------
template<int T> __device__ __forceinline__ void fgstep(
    const float* xp, float* op, float ring[26], float& run, float x0, float& x95,
    float zr0, float zi0, float zr1, float zi1, float zr2, float zi2)
{
  float cur = ring[T % 26];
  constexpr float g0r=(float)Gre_(1,T), g0i=(float)Gim_(1,T);
  constexpr float g1r=(float)Gre_(4,T), g1i=(float)Gim_(4,T);
  constexpr float g2r=(float)Gre_(5,T), g2i=(float)Gim_(5,T);
  float oy = fmaf(zr0,g0r, fmaf(-zi0,g0i, fmaf(zr1,g1r, fmaf(-zi1,g1i, fmaf(zr2,g2r, -zi2*g2i)))));
  op[T*DM] = fmaf(run, -(1.0f/25.0f), cur) + oy;
  float subv = (T-12 >= 0) ? ring[(T+14) % 26] : x0;
  float addv;
  if constexpr (T+13 <= 95) addv = xp[(T+13)*DM]; else addv = x95;
  if constexpr (T+13 == 95) x95 = addv;
  ring[(T+13) % 26] = addv;
  run += addv - subv;
}
template<int T> __device__ __forceinline__ void fgloop(
    const float* xp, float* op, float ring[26], float& run, float x0, float& x95,
    float zr0, float zi0, float zr1, float zi1, float zr2, float zi2)
{
  if constexpr (T < LSEQ){
    fgstep<T>(xp, op, ring, run, x0, x95, zr0, zi0, zr1, zi1, zr2, zi2);
    fgloop<T+1>(xp, op, ring, run, x0, x95, zr0, zi0, zr1, zi1, zr2, zi2);
  }
}

// One warp per (b,n) tile of [96 x 32], lane == channel d. 2 warps/block, grid 8000.
__global__ __launch_bounds__(64, 8)
void feldm_kernel(const float* __restrict__ x,
                  const float* __restrict__ Wq,
                  const float* __restrict__ Wo,
                  const float* __restrict__ W1,
                  const float* __restrict__ W2,
                  float* __restrict__ out)
{
    __shared__ float  xbuf[2][LSEQ * DM];   // per-warp x tile (12KB each)
    __shared__ float4 scr4[2][DM];          // 3-mode complex exchange (modes 0,1)
    __shared__ float2 scr2[2][DM];          // mode 2

    const int tid  = threadIdx.x;
    const int warp = tid >> 5;
    const int lane = tid & 31;

    const int unit = blockIdx.x * 2 + warp;     // b*2000 + n
    const int n    = unit % 2000;
    const float* __restrict__ xu = x   + (size_t)unit * (LSEQ * DM);
    float* __restrict__       ou = out + (size_t)unit * (LSEQ * DM);

    // ---- stage x tile into smem (24 x 16B per lane, one MLP batch) ----
    {
        unsigned int sbase = (unsigned int)__cvta_generic_to_shared(&xbuf[warp][0]);
        const float4* gsrc = (const float4*)xu;
        #pragma unroll
        for (int k = 0; k < 24; ++k) {
            int idx = k * 32 + lane;
            cp_async16(sbase + idx * 16, gsrc + idx);
        }
        cp_commit();
    }
    cp_wait0();
    __syncwarp();

    const float* xp = &xbuf[warp][lane];

    // ---- Phase B: 3-mode DFT along l (rfft sign e^{-iwl}) ----
    Acc6 a = {0.f,0.f,0.f,0.f,0.f,0.f};
    bloop<0>(a, xp);
    scr4[warp][lane] = make_float4(a.ar0, a.ai0, a.ar1, a.ai1);
    scr2[warp][lane] = make_float2(a.ar2, a.ai2);
    __syncwarp();

    // ---- Phase C: Xq[c,m] = sum_d Wq[c,d] * Xx[d,m]  (bq only feeds mode 0 -> drops) ----
    float wrow[32];
    #pragma unroll
    for (int j = 0; j < 8; ++j) {
        float4 v = *(const float4*)&Wq[lane * 32 + 4 * j];
        wrow[4*j] = v.x; wrow[4*j+1] = v.y; wrow[4*j+2] = v.z; wrow[4*j+3] = v.w;
    }
    float qr0=0.f,qi0=0.f,qr1=0.f,qi1=0.f,qr2=0.f,qi2=0.f;
    #pragma unroll
    for (int d = 0; d < 32; ++d) {
        float4 t0 = scr4[warp][d];
        float2 t1 = scr2[warp][d];
        float w = wrow[d];
        qr0 = fmaf(w, t0.x, qr0); qi0 = fmaf(w, t0.y, qi0);
        qr1 = fmaf(w, t0.z, qr1); qi1 = fmaf(w, t0.w, qi1);
        qr2 = fmaf(w, t1.x, qr2); qi2 = fmaf(w, t1.y, qi2);
    }
    __syncwarp();
    scr4[warp][lane] = make_float4(qr0, qi0, qr1, qi1);
    scr2[warp][lane] = make_float2(qr2, qi2);
    __syncwarp();

    // ---- Phase D: per-head complex 8x8 mix with (W1 + i W2)[n,h,:,:,m] ----
    const int h = lane >> 3, o = lane & 7;
    const float* __restrict__ w1p = W1 + ((size_t)n * 4 + h) * 192;
    const float* __restrict__ w2p = W2 + ((size_t)n * 4 + h) * 192;
    float or0=0.f,oi0=0.f,or1=0.f,oi1=0.f,or2=0.f,oi2=0.f;
    #pragma unroll
    for (int e = 0; e < 8; ++e) {
        float4 t0 = scr4[warp][h * 8 + e];
        float2 t1 = scr2[warp][h * 8 + e];
        int widx = (e * 8 + o) * 3;
        float a0 = w1p[widx+0], a1 = w1p[widx+1], a2 = w1p[widx+2];
        float b0 = w2p[widx+0], b1 = w2p[widx+1], b2 = w2p[widx+2];
        or0 += t0.x*a0 - t0.y*b0;  oi0 += t0.x*b0 + t0.y*a0;
        or1 += t0.z*a1 - t0.w*b1;  oi1 += t0.z*b1 + t0.w*a1;
        or2 += t1.x*a2 - t1.y*b2;  oi2 += t1.x*b2 + t1.y*a2;
    }
    __syncwarp();
    scr4[warp][lane] = make_float4(or0, oi0, or1, oi1);
    scr2[warp][lane] = make_float2(or2, oi2);
    __syncwarp();

    // ---- Phase E: Z[dout,m] = (2/96) * sum_c O[c,m] * Wo[dout,c] ----
    #pragma unroll
    for (int j = 0; j < 8; ++j) {
        float4 v = *(const float4*)&Wo[lane * 32 + 4 * j];
        wrow[4*j] = v.x; wrow[4*j+1] = v.y; wrow[4*j+2] = v.z; wrow[4*j+3] = v.w;
    }
    float zr0=0.f,zi0=0.f,zr1=0.f,zi1=0.f,zr2=0.f,zi2=0.f;
    #pragma unroll
    for (int c = 0; c < 32; ++c) {
        float4 t0 = scr4[warp][c];
        float2 t1 = scr2[warp][c];
        float w = wrow[c];
        zr0 = fmaf(w, t0.x, zr0); zi0 = fmaf(w, t0.y, zi0);
        zr1 = fmaf(w, t0.z, zr1); zi1 = fmaf(w, t0.w, zi1);
        zr2 = fmaf(w, t1.x, zr2); zi2 = fmaf(w, t1.y, zi2);
    }
    const float inv = 2.0f / 96.0f;
    zr0 *= inv; zi0 *= inv; zr1 *= inv; zi1 *= inv; zr2 *= inv; zi2 *= inv;
    // NOTE: bo cancels exactly in (xr - movavg(xr)) since every window averages 25 values.

    // ---- Phases F+G fused: out[t] = (x[t] - run/25) + Re(sum_m Z_m G_m(t)) ----
    float ring[26];
    #pragma unroll
    for (int j = 0; j < 13; ++j) ring[j] = xp[j*DM];
    float x0 = ring[0], x95 = 0.f;
    float run = 12.0f * x0;
    #pragma unroll
    for (int j = 0; j < 13; ++j) run += ring[j];

    fgloop<0>(xp, ou + lane, ring, run, x0, x95, zr0, zi0, zr1, zi1, zr2, zi2);
}

extern "C" void kernel_launch(void* const* d_in, const int* in_sizes, int n_in,
                              void* d_out, int out_size) {
    // metadata order: x, Wq, bq, Wk, bk, Wv, bv, Wo, bo, W1, W2
    const float* x  = (const float*)d_in[0];
    const float* Wq = (const float*)d_in[1];
    const float* Wo = (const float*)d_in[7];
    const float* W1 = (const float*)d_in[9];
    const float* W2 = (const float*)d_in[10];
    feldm_kernel<<<8000, 64>>>(x, Wq, Wo, W1, W2, (float*)d_out);
}